// round 4
// baseline (speedup 1.0000x reference)
#include <cuda_runtime.h>
#include <math_constants.h>

namespace {

constexpr int TOKENS   = 16384;
constexpr int NEXP     = 64;
constexpr int KDIM     = 2048;
constexpr int K_TOP    = 6;
constexpr int TILE_M   = 64;     // tokens per block
constexpr int KC       = 16;     // k-chunk
constexpr int NCH      = KDIM / KC;   // 128 chunks
constexpr int NTHREADS = 128;
constexpr float FP32_MIN_NORMAL = 1.17549435e-38f;  // 2^-126

struct __align__(16) Smem {
  union {
    struct {
      float2 xs[2][TILE_M][KC + 1];   // [buf][token][k] : value duplicated {x,x}
      float  ws[2][KC][NEXP + 4];     // [buf][k][expert]
    } mm;
    float logits[TILE_M][NEXP + 1];
  };
};

__device__ __forceinline__ void fma2(unsigned long long& d,
                                     unsigned long long a,
                                     unsigned long long b) {
  // packed fp32x2 fused MAC (Blackwell): 2 IEEE FMAs per instruction
  asm("fma.rn.f32x2 %0, %1, %2, %0;" : "+l"(d) : "l"(a), "l"(b));
}

}  // namespace

__global__ void __launch_bounds__(NTHREADS, 2)
gate_kernel(const float* __restrict__ x, const float* __restrict__ w,
            float* __restrict__ outw, float* __restrict__ outi)
{
  __shared__ Smem sm;

  const int tid   = threadIdx.x;
  const int ecol  = tid & 15;     // experts ecol*4 .. +3
  const int trow  = tid >> 4;     // tokens  trow*8 .. +7
  const int tile0 = blockIdx.x * TILE_M;

  // ---- global-load indexing: 256 float4 of x + 256 float4 of w per chunk --
  const int fA = tid;
  const int fB = tid + NTHREADS;
  const int tokA = fA >> 2, k4A = fA & 3;
  const int tokB = fB >> 2, k4B = fB & 3;

  const float4* __restrict__ x4 = reinterpret_cast<const float4*>(x);
  const float4* __restrict__ w4 = reinterpret_cast<const float4*>(w);
  const int rowF4 = KDIM / 4;

  const long ixA = (long)(tile0 + tokA) * rowF4 + k4A;
  const long ixB = (long)(tile0 + tokB) * rowF4 + k4B;
  const long iwA = (long)tokA * rowF4 + k4A;   // tokA/tokB double as expert ids
  const long iwB = (long)tokB * rowF4 + k4B;

  float4 xa, xb, wa, wb;

  // ---- prologue: chunk 0 -> buf 0 ----------------------------------------
  xa = x4[ixA]; xb = x4[ixB];
  wa = w4[iwA]; wb = w4[iwB];
  {
    sm.mm.xs[0][tokA][k4A * 4 + 0] = make_float2(xa.x, xa.x);
    sm.mm.xs[0][tokA][k4A * 4 + 1] = make_float2(xa.y, xa.y);
    sm.mm.xs[0][tokA][k4A * 4 + 2] = make_float2(xa.z, xa.z);
    sm.mm.xs[0][tokA][k4A * 4 + 3] = make_float2(xa.w, xa.w);
    sm.mm.xs[0][tokB][k4B * 4 + 0] = make_float2(xb.x, xb.x);
    sm.mm.xs[0][tokB][k4B * 4 + 1] = make_float2(xb.y, xb.y);
    sm.mm.xs[0][tokB][k4B * 4 + 2] = make_float2(xb.z, xb.z);
    sm.mm.xs[0][tokB][k4B * 4 + 3] = make_float2(xb.w, xb.w);

    sm.mm.ws[0][k4A * 4 + 0][tokA] = wa.x;
    sm.mm.ws[0][k4A * 4 + 1][tokA] = wa.y;
    sm.mm.ws[0][k4A * 4 + 2][tokA] = wa.z;
    sm.mm.ws[0][k4A * 4 + 3][tokA] = wa.w;
    sm.mm.ws[0][k4B * 4 + 0][tokB] = wb.x;
    sm.mm.ws[0][k4B * 4 + 1][tokB] = wb.y;
    sm.mm.ws[0][k4B * 4 + 2][tokB] = wb.z;
    sm.mm.ws[0][k4B * 4 + 3][tokB] = wb.w;
  }
  __syncthreads();

  // ---- accumulators: 2 expert-pairs x 8 tokens, each f32x2 ----------------
  unsigned long long acc[2][8];
#pragma unroll
  for (int ep = 0; ep < 2; ++ep)
#pragma unroll
    for (int t = 0; t < 8; ++t) acc[ep][t] = 0ULL;

  // ---- mainloop -----------------------------------------------------------
  for (int c = 0; c < NCH; ++c) {
    const int buf = c & 1;

    if (c + 1 < NCH) {
      const long off = (long)(c + 1) * (KC / 4);
      xa = x4[ixA + off]; xb = x4[ixB + off];
      wa = w4[iwA + off]; wb = w4[iwB + off];
    }

#pragma unroll
    for (int kk = 0; kk < KC; ++kk) {
      const float* wrow = &sm.mm.ws[buf][kk][ecol * 4];
      const unsigned long long wp0 =
          *reinterpret_cast<const unsigned long long*>(wrow);
      const unsigned long long wp1 =
          *reinterpret_cast<const unsigned long long*>(wrow + 2);
#pragma unroll
      for (int t = 0; t < 8; ++t) {
        const unsigned long long xd =
            *reinterpret_cast<const unsigned long long*>(
                &sm.mm.xs[buf][trow * 8 + t][kk]);
        fma2(acc[0][t], wp0, xd);
        fma2(acc[1][t], wp1, xd);
      }
    }

    if (c + 1 < NCH) {
      const int nb = buf ^ 1;
      sm.mm.xs[nb][tokA][k4A * 4 + 0] = make_float2(xa.x, xa.x);
      sm.mm.xs[nb][tokA][k4A * 4 + 1] = make_float2(xa.y, xa.y);
      sm.mm.xs[nb][tokA][k4A * 4 + 2] = make_float2(xa.z, xa.z);
      sm.mm.xs[nb][tokA][k4A * 4 + 3] = make_float2(xa.w, xa.w);
      sm.mm.xs[nb][tokB][k4B * 4 + 0] = make_float2(xb.x, xb.x);
      sm.mm.xs[nb][tokB][k4B * 4 + 1] = make_float2(xb.y, xb.y);
      sm.mm.xs[nb][tokB][k4B * 4 + 2] = make_float2(xb.z, xb.z);
      sm.mm.xs[nb][tokB][k4B * 4 + 3] = make_float2(xb.w, xb.w);

      sm.mm.ws[nb][k4A * 4 + 0][tokA] = wa.x;
      sm.mm.ws[nb][k4A * 4 + 1][tokA] = wa.y;
      sm.mm.ws[nb][k4A * 4 + 2][tokA] = wa.z;
      sm.mm.ws[nb][k4A * 4 + 3][tokA] = wa.w;
      sm.mm.ws[nb][k4B * 4 + 0][tokB] = wb.x;
      sm.mm.ws[nb][k4B * 4 + 1][tokB] = wb.y;
      sm.mm.ws[nb][k4B * 4 + 2][tokB] = wb.z;
      sm.mm.ws[nb][k4B * 4 + 3][tokB] = wb.w;
    }
    __syncthreads();
  }

  // ---- epilogue: logits -> smem -------------------------------------------
#pragma unroll
  for (int ep = 0; ep < 2; ++ep)
#pragma unroll
    for (int t = 0; t < 8; ++t) {
      float2 v = *reinterpret_cast<float2*>(&acc[ep][t]);
      const int tok = trow * 8 + t;
      const int e0  = ecol * 4 + ep * 2;
      sm.logits[tok][e0]     = v.x;
      sm.logits[tok][e0 + 1] = v.y;
    }
  __syncthreads();

  // ---- per-token softmax (FTZ like XLA:GPU) + stable top-6 ----------------
  if (tid < TILE_M) {
    const float* row = sm.logits[tid];

    float mx = -CUDART_INF_F;
#pragma unroll 8
    for (int e = 0; e < NEXP; ++e) mx = fmaxf(mx, row[e]);

    float sum = 0.0f;
#pragma unroll 8
    for (int e = 0; e < NEXP; ++e) sum += expf(row[e] - mx);

    float bv[K_TOP];
    int   bi[K_TOP];
#pragma unroll
    for (int j = 0; j < K_TOP; ++j) { bv[j] = -CUDART_INF_F; bi[j] = 0; }

    for (int e = 0; e < NEXP; ++e) {
      float s = expf(row[e] - mx) / sum;
      // XLA:GPU softmax runs with flush-to-zero: subnormal scores become
      // exactly 0.0, and top_k then tie-breaks among the zeros by lowest
      // index. Replicate the flush so our tie set matches the reference's.
      if (s < FP32_MIN_NORMAL) s = 0.0f;
      if (s > bv[K_TOP - 1]) {
        bv[K_TOP - 1] = s;
        bi[K_TOP - 1] = e;
        // strict '>' keeps lowest-index-first ordering among equal scores,
        // matching jax.lax.top_k's stable descending sort.
#pragma unroll
        for (int j = K_TOP - 1; j > 0; --j) {
          if (bv[j] > bv[j - 1]) {
            const float tv = bv[j]; bv[j] = bv[j - 1]; bv[j - 1] = tv;
            const int   ti = bi[j]; bi[j] = bi[j - 1]; bi[j - 1] = ti;
          }
        }
      }
    }

    const long gt = tile0 + tid;
#pragma unroll
    for (int j = 0; j < K_TOP; ++j) {
      outw[gt * K_TOP + j] = bv[j];
      outi[gt * K_TOP + j] = (float)bi[j];
    }
  }
}

extern "C" void kernel_launch(void* const* d_in, const int* in_sizes, int n_in,
                              void* d_out, int out_size) {
  const float* a = (const float*)d_in[0];
  const float* b = (const float*)d_in[1];
  const float* x = a;
  const float* w = b;
  if (n_in >= 2 && in_sizes[0] == NEXP * KDIM && in_sizes[1] == TOKENS * KDIM) {
    x = b; w = a;
  }

  float* out  = (float*)d_out;
  float* outw = out;                         // weights [16384, 6]
  float* outi = out + (long)TOKENS * K_TOP;  // indices (as float) [16384, 6]

  gate_kernel<<<TOKENS / TILE_M, NTHREADS>>>(x, w, outw, outi);
}